// round 1
// baseline (speedup 1.0000x reference)
#include <cuda_runtime.h>
#include <cstdint>

#define NTOK   8192
#define NEXP   16
#define CAP    512
#define FDIM   512
#define IDIM   1024
#define TI3    3072
#define SEQ    2048

// ---------------- scratch (static device allocation; no cudaMalloc) ----------------
#define OFF_XIN   0u
#define OFF_BIG   4194304u
#define OFF_TN1   29360128u
#define OFF_TN2   37748736u
#define OFF_Y2    46137344u
#define OFF_GATES 50331648u
#define OFF_SCALE 50462720u
#define OFF_W1T   50470912u
#define SCRATCH_FLOATS 59908096u

__device__ float g_scratch[SCRATCH_FLOATS];
__device__ int   g_iscr[131072 + 8192 + 8192];   // ord | perm | inv

// ---------------- transposes ----------------
__global__ void k_transpose_in(const float* __restrict__ in, float* __restrict__ out) {
    __shared__ float tile[32][33];
    int b = blockIdx.z;
    int s0 = blockIdx.x * 32, f0 = blockIdx.y * 32;
    int tx = threadIdx.x, ty = threadIdx.y;
    #pragma unroll
    for (int r = ty; r < 32; r += 8)
        tile[r][tx] = in[((size_t)(b * FDIM + f0 + r)) * SEQ + s0 + tx];
    __syncthreads();
    #pragma unroll
    for (int r = ty; r < 32; r += 8)
        out[((size_t)(b * SEQ + s0 + r)) * FDIM + f0 + tx] = tile[tx][r];
}

__global__ void k_transpose_out(const float* __restrict__ y2, float* __restrict__ out) {
    __shared__ float tile[32][33];
    int b = blockIdx.z;
    int s0 = blockIdx.x * 32, f0 = blockIdx.y * 32;
    int tx = threadIdx.x, ty = threadIdx.y;
    #pragma unroll
    for (int r = ty; r < 32; r += 8)
        tile[r][tx] = y2[((size_t)(b * SEQ + s0 + r)) * FDIM + f0 + tx]; // tile[srel][frel]
    __syncthreads();
    #pragma unroll
    for (int r = ty; r < 32; r += 8)
        out[((size_t)(b * FDIM + f0 + r)) * SEQ + s0 + tx] = tile[tx][r];
}

// w1 [O=3072][I=1024][k=3] -> w1t [k][i][o]  (GEMM-friendly: row kk, col o)
__global__ void k_w1t(const float* __restrict__ w1, float* __restrict__ w1t) {
    __shared__ float tile[32][33];
    int k = blockIdx.z;
    int o0 = blockIdx.x * 32, i0 = blockIdx.y * 32;
    int tx = threadIdx.x, ty = threadIdx.y;
    #pragma unroll
    for (int r = ty; r < 32; r += 8)
        tile[r][tx] = w1[((size_t)(o0 + r) * IDIM + i0 + tx) * 3 + k];
    __syncthreads();
    #pragma unroll
    for (int r = ty; r < 32; r += 8)
        w1t[((size_t)k * IDIM + i0 + r) * TI3 + o0 + tx] = tile[tx][r];
}

// ---------------- gate logits + softmax ----------------
// block = 256 threads = 16 tokens x 16 experts
__global__ __launch_bounds__(256) void k_logits(const float* __restrict__ X,
                                                const float* __restrict__ G,
                                                float* __restrict__ gates, int K) {
    __shared__ float Xs[16][65];
    __shared__ float Gs[64][16];
    int t0 = blockIdx.x * 16;
    int tid = threadIdx.x;
    int e = tid & 15, tl = tid >> 4;
    float acc = 0.f;
    for (int k0 = 0; k0 < K; k0 += 64) {
        __syncthreads();
        #pragma unroll
        for (int r = 0; r < 4; r++) {
            int j = tid + 256 * r;
            int row = j >> 6, col = j & 63;
            Xs[row][col] = X[(size_t)(t0 + row) * K + k0 + col];
        }
        #pragma unroll
        for (int r = 0; r < 4; r++) {
            int j = tid + 256 * r;
            int kk = j >> 4, ee = j & 15;
            Gs[kk][ee] = G[(size_t)(k0 + kk) * NEXP + ee];
        }
        __syncthreads();
        #pragma unroll
        for (int k = 0; k < 64; k++) acc += Xs[tl][k] * Gs[k][e];
    }
    float m = acc;
    #pragma unroll
    for (int o = 8; o >= 1; o >>= 1) m = fmaxf(m, __shfl_xor_sync(0xffffffffu, m, o, 16));
    float ex = expf(acc - m);
    float s = ex;
    #pragma unroll
    for (int o = 8; o >= 1; o >>= 1) s += __shfl_xor_sync(0xffffffffu, s, o, 16);
    gates[(size_t)(t0 + tl) * NEXP + e] = ex / s;
}

// ---------------- per-expert full descending sort (bitonic, 16 blocks) ----------------
extern __shared__ unsigned long long smsort[];
__global__ __launch_bounds__(1024) void k_sort(const float* __restrict__ gates,
                                               int* __restrict__ ord) {
    int e = blockIdx.x;
    int tid = threadIdx.x;
    #pragma unroll
    for (int r = 0; r < 8; r++) {
        int i = r * 1024 + tid;
        float v = gates[(size_t)i * NEXP + e];               // v >= 0 (softmax)
        unsigned fb = __float_as_uint(v);
        smsort[i] = ((unsigned long long)fb << 32) | (unsigned)(NTOK - 1 - i); // lower idx wins ties
    }
    __syncthreads();
    for (int k = 2; k <= NTOK; k <<= 1) {
        for (int j = k >> 1; j > 0; j >>= 1) {
            #pragma unroll
            for (int r = 0; r < 8; r++) {
                int i = r * 1024 + tid;
                int l = i ^ j;
                if (l > i) {
                    unsigned long long a = smsort[i], b = smsort[l];
                    bool desc = ((i & k) == 0);
                    if ((a < b) == desc) { smsort[i] = b; smsort[l] = a; }
                }
            }
            __syncthreads();
        }
    }
    #pragma unroll
    for (int r = 0; r < 8; r++) {
        int i = r * 1024 + tid;
        ord[e * NTOK + i] = NTOK - 1 - (int)(unsigned)(smsort[i] & 0xffffffffu);
    }
}

// ---------------- greedy capacity assignment (1 block) ----------------
__global__ __launch_bounds__(1024) void k_greedy(const int* __restrict__ ord,
                                                 int* __restrict__ perm) {
    __shared__ unsigned assigned[NTOK / 32];
    __shared__ int wsums[32];
    int tid = threadIdx.x;
    int lane = tid & 31, wid = tid >> 5;
    if (tid < NTOK / 32) assigned[tid] = 0u;
    __syncthreads();

    for (int e = 0; e < NEXP; e++) {
        int toks[8];
        int flags = 0, cnt = 0;
        #pragma unroll
        for (int i = 0; i < 8; i++) {
            int tok = ord[e * NTOK + tid * 8 + i];
            toks[i] = tok;
            bool freetok = !((assigned[tok >> 5] >> (tok & 31)) & 1u);
            flags |= ((int)freetok) << i;
            cnt += (int)freetok;
        }
        // block exclusive scan of cnt (rank order == thread order)
        int v = cnt;
        #pragma unroll
        for (int o = 1; o < 32; o <<= 1) {
            int n = __shfl_up_sync(0xffffffffu, v, o);
            if (lane >= o) v += n;
        }
        if (lane == 31) wsums[wid] = v;
        __syncthreads();
        if (wid == 0) {
            int w = wsums[lane];
            #pragma unroll
            for (int o = 1; o < 32; o <<= 1) {
                int n = __shfl_up_sync(0xffffffffu, w, o);
                if (lane >= o) w += n;
            }
            wsums[lane] = w;
        }
        __syncthreads();
        int r = v - cnt + (wid ? wsums[wid - 1] : 0);
        #pragma unroll
        for (int i = 0; i < 8; i++) {
            if ((flags >> i) & 1) {
                if (r < CAP) {
                    int tok = toks[i];
                    perm[r * NEXP + e] = tok;
                    atomicOr(&assigned[tok >> 5], 1u << (tok & 31));
                }
                r++;
            }
        }
        __syncthreads();
    }
}

__global__ void k_scatter_inv(const int* __restrict__ perm, int* __restrict__ inv) {
    int p = blockIdx.x * 256 + threadIdx.x;
    inv[perm[p]] = p;
}

__global__ void k_scale(const int* __restrict__ inv, const float* __restrict__ gates,
                        float* __restrict__ scl) {
    int t = blockIdx.x * 256 + threadIdx.x;
    scl[t] = gates[(size_t)t * NEXP + (inv[t] >> 9)];   // expert_index = inv // 512
}

// ---------------- grouped MoE GEMM: gather rows, scale, GEMM, scatter rows ----------------
__global__ __launch_bounds__(256) void k_gemm_moe(const float* __restrict__ X,
                                                  const float* __restrict__ W,
                                                  const int* __restrict__ perm,
                                                  const float* __restrict__ scl,
                                                  float* __restrict__ Y, int K, int N) {
    __shared__ float As[8][128];
    __shared__ float Bs[8][128];
    __shared__ int   stok[128];
    __shared__ float ssc[128];

    int e  = blockIdx.z;
    int n0 = blockIdx.x * 128;
    int m0 = blockIdx.y * 128;
    int tid = threadIdx.x;

    if (tid < 128) {
        int tok = perm[(m0 + tid) * NEXP + e];
        stok[tid] = tok;
        ssc[tid]  = scl[tok];
    }
    __syncthreads();

    const float* Wb = W + (size_t)e * K * N;
    int tx = tid & 15, ty = tid >> 4;
    int aM = tid >> 1, aK = (tid & 1) * 4;
    int bK = tid >> 5, bN = (tid & 31) * 4;

    const float* Arow = X + (size_t)stok[aM] * K + aK;
    float asc = ssc[aM];
    const float* Bptr = Wb + (size_t)bK * N + n0 + bN;

    float acc[8][8];
    #pragma unroll
    for (int i = 0; i < 8; i++)
        #pragma unroll
        for (int j = 0; j < 8; j++) acc[i][j] = 0.f;

    for (int k0 = 0; k0 < K; k0 += 8) {
        float4 av = *(const float4*)(Arow + k0);
        float4 bv = *(const float4*)(Bptr + (size_t)k0 * N);
        __syncthreads();
        As[aK + 0][aM] = av.x * asc; As[aK + 1][aM] = av.y * asc;
        As[aK + 2][aM] = av.z * asc; As[aK + 3][aM] = av.w * asc;
        *(float4*)&Bs[bK][bN] = bv;
        __syncthreads();
        #pragma unroll
        for (int k = 0; k < 8; k++) {
            float a[8], b[8];
            *(float4*)&a[0] = *(const float4*)&As[k][ty * 8];
            *(float4*)&a[4] = *(const float4*)&As[k][ty * 8 + 4];
            *(float4*)&b[0] = *(const float4*)&Bs[k][tx * 8];
            *(float4*)&b[4] = *(const float4*)&Bs[k][tx * 8 + 4];
            #pragma unroll
            for (int i = 0; i < 8; i++)
                #pragma unroll
                for (int j = 0; j < 8; j++) acc[i][j] += a[i] * b[j];
        }
    }
    #pragma unroll
    for (int i = 0; i < 8; i++) {
        int tok = stok[ty * 8 + i];
        float* yr = Y + (size_t)tok * N + n0 + tx * 8;
        *(float4*)yr       = make_float4(acc[i][0], acc[i][1], acc[i][2], acc[i][3]);
        *(float4*)(yr + 4) = make_float4(acc[i][4], acc[i][5], acc[i][6], acc[i][7]);
    }
}

// ---------------- causal conv as one GEMM (logical K = 3*1024, shifted A) ----------------
__global__ __launch_bounds__(256) void k_gemm_conv(const float* __restrict__ X,
                                                   const float* __restrict__ W,
                                                   float* __restrict__ Y) {
    __shared__ float As[8][128];
    __shared__ float Bs[8][128];

    int n0 = blockIdx.x * 128;
    int m0 = blockIdx.y * 128;
    int tid = threadIdx.x;
    int tx = tid & 15, ty = tid >> 4;
    int aM = tid >> 1, aK = (tid & 1) * 4;
    int bK = tid >> 5, bN = (tid & 31) * 4;

    int t = m0 + aM;
    int s = t & (SEQ - 1);
    const float* Bptr = W + (size_t)bK * TI3 + n0 + bN;

    float acc[8][8];
    #pragma unroll
    for (int i = 0; i < 8; i++)
        #pragma unroll
        for (int j = 0; j < 8; j++) acc[i][j] = 0.f;

    for (int k0 = 0; k0 < TI3; k0 += 8) {
        int kk  = k0 + aK;
        int kid = kk >> 10;        // conv tap 0..2
        int i0  = kk & 1023;
        float4 av = make_float4(0.f, 0.f, 0.f, 0.f);
        if (s + kid >= 2)
            av = *(const float4*)(X + (size_t)(t + kid - 2) * IDIM + i0);
        float4 bv = *(const float4*)(Bptr + (size_t)k0 * TI3);
        __syncthreads();
        As[aK + 0][aM] = av.x; As[aK + 1][aM] = av.y;
        As[aK + 2][aM] = av.z; As[aK + 3][aM] = av.w;
        *(float4*)&Bs[bK][bN] = bv;
        __syncthreads();
        #pragma unroll
        for (int k = 0; k < 8; k++) {
            float a[8], b[8];
            *(float4*)&a[0] = *(const float4*)&As[k][ty * 8];
            *(float4*)&a[4] = *(const float4*)&As[k][ty * 8 + 4];
            *(float4*)&b[0] = *(const float4*)&Bs[k][tx * 8];
            *(float4*)&b[4] = *(const float4*)&Bs[k][tx * 8 + 4];
            #pragma unroll
            for (int i = 0; i < 8; i++)
                #pragma unroll
                for (int j = 0; j < 8; j++) acc[i][j] += a[i] * b[j];
        }
    }
    #pragma unroll
    for (int i = 0; i < 8; i++) {
        float* yr = Y + (size_t)(m0 + ty * 8 + i) * TI3 + n0 + tx * 8;
        *(float4*)yr       = make_float4(acc[i][0], acc[i][1], acc[i][2], acc[i][3]);
        *(float4*)(yr + 4) = make_float4(acc[i][4], acc[i][5], acc[i][6], acc[i][7]);
    }
}

// ---------------- triple norm: relu(s0)^3*s1+shift, center, L2-normalize * sqrt(1024) ----------------
__global__ __launch_bounds__(256) void k_triple_norm(const float* __restrict__ Y,
                                                     float* __restrict__ Z) {
    __shared__ float sm[8];
    int t = blockIdx.x;
    int tid = threadIdx.x;
    const float* row = Y + (size_t)t * TI3;

    float v[4];
    float ls = 0.f;
    #pragma unroll
    for (int i = 0; i < 4; i++) {
        int c = tid + 256 * i;
        float r = fmaxf(row[c], 0.f);
        v[i] = r * r * r * row[IDIM + c] + row[2 * IDIM + c];
        ls += v[i];
    }
    #pragma unroll
    for (int o = 16; o >= 1; o >>= 1) ls += __shfl_xor_sync(0xffffffffu, ls, o);
    if ((tid & 31) == 0) sm[tid >> 5] = ls;
    __syncthreads();
    float mean = (sm[0] + sm[1] + sm[2] + sm[3] + sm[4] + sm[5] + sm[6] + sm[7]) * (1.0f / 1024.0f);
    __syncthreads();

    float ss = 0.f;
    #pragma unroll
    for (int i = 0; i < 4; i++) {
        float d = v[i] - mean;
        ss += d * d;
    }
    #pragma unroll
    for (int o = 16; o >= 1; o >>= 1) ss += __shfl_xor_sync(0xffffffffu, ss, o);
    if ((tid & 31) == 0) sm[tid >> 5] = ss;
    __syncthreads();
    float tot = sm[0] + sm[1] + sm[2] + sm[3] + sm[4] + sm[5] + sm[6] + sm[7];
    float rstd = sqrtf(1024.0f / tot);
    #pragma unroll
    for (int i = 0; i < 4; i++)
        Z[(size_t)t * IDIM + tid + 256 * i] = (v[i] - mean) * rstd;
}

// ---------------- host ----------------
extern "C" void kernel_launch(void* const* d_in, const int* in_sizes, int n_in,
                              void* d_out, int out_size) {
    const float* inp   = (const float*)d_in[0];
    const float* w0    = (const float*)d_in[1];
    const float* gate0 = (const float*)d_in[2];
    const float* w1    = (const float*)d_in[3];
    const float* w2    = (const float*)d_in[4];
    const float* gate2 = (const float*)d_in[5];
    float* out = (float*)d_out;

    void* p;  cudaGetSymbolAddress(&p, g_scratch);
    void* pi; cudaGetSymbolAddress(&pi, g_iscr);
    float* fs = (float*)p;
    int*   is = (int*)pi;

    float* xin   = fs + OFF_XIN;
    float* big   = fs + OFF_BIG;
    float* tn1   = fs + OFF_TN1;
    float* tn2   = fs + OFF_TN2;
    float* y2    = fs + OFF_Y2;
    float* gates = fs + OFF_GATES;
    float* scl   = fs + OFF_SCALE;
    float* w1t   = fs + OFF_W1T;
    int* ord  = is;
    int* perm = is + 131072;
    int* inv  = is + 131072 + 8192;

    cudaFuncSetAttribute(k_sort, cudaFuncAttributeMaxDynamicSharedMemorySize, 65536);

    // ---- MoE 1 ----
    k_transpose_in<<<dim3(64, 16, 4), dim3(32, 8)>>>(inp, xin);
    k_logits<<<512, 256>>>(xin, gate0, gates, FDIM);
    k_sort<<<16, 1024, 65536>>>(gates, ord);
    k_greedy<<<1, 1024>>>(ord, perm);
    k_scatter_inv<<<32, 256>>>(perm, inv);
    k_scale<<<32, 256>>>(inv, gates, scl);
    k_gemm_moe<<<dim3(24, 4, 16), 256>>>(xin, w0, perm, scl, big, FDIM, TI3);
    k_triple_norm<<<8192, 256>>>(big, tn1);

    // ---- causal conv ----
    k_w1t<<<dim3(96, 32, 3), dim3(32, 8)>>>(w1, w1t);
    k_gemm_conv<<<dim3(24, 64), 256>>>(tn1, w1t, big);
    k_triple_norm<<<8192, 256>>>(big, tn2);

    // ---- MoE 2 ----
    k_logits<<<512, 256>>>(tn2, gate2, gates, IDIM);
    k_sort<<<16, 1024, 65536>>>(gates, ord);
    k_greedy<<<1, 1024>>>(ord, perm);
    k_scatter_inv<<<32, 256>>>(perm, inv);
    k_scale<<<32, 256>>>(inv, gates, scl);
    k_gemm_moe<<<dim3(4, 4, 16), 256>>>(tn2, w2, perm, scl, y2, IDIM, FDIM);

    k_transpose_out<<<dim3(64, 16, 4), dim3(32, 8)>>>(y2, out);
}

// round 6
// speedup vs baseline: 1.1967x; 1.1967x over previous
#include <cuda_runtime.h>
#include <cstdint>

#define NTOK   8192
#define NEXP   16
#define CAP    512
#define FDIM   512
#define IDIM   1024
#define TI3    3072
#define SEQ    2048

#define OFF_XIN   0u
#define OFF_BIG   4194304u
#define OFF_TN1   29360128u
#define OFF_TN2   37748736u
#define OFF_Y2    46137344u
#define OFF_GATES 50331648u
#define OFF_SCALE 50462720u
#define OFF_W1T   50470912u
#define OFF_AG    59908096u
#define SCRATCH_FLOATS 68296704u

__device__ float g_scratch[SCRATCH_FLOATS];
__device__ int   g_iscr[131072 + 8192 + 8192];   // ord | perm | inv

__device__ __forceinline__ uint32_t s2u(const void* p) {
    uint32_t r;
    asm("{ .reg .u64 t; cvta.to.shared.u64 t, %1; cvt.u32.u64 %0, t; }" : "=r"(r) : "l"(p));
    return r;
}
__device__ __forceinline__ void cpasync16(uint32_t dst, const void* src) {
    asm volatile("cp.async.cg.shared.global [%0], [%1], 16;" :: "r"(dst), "l"(src));
}
#define CP_COMMIT() asm volatile("cp.async.commit_group;" ::: "memory")
#define CP_WAIT0()  asm volatile("cp.async.wait_group 0;" ::: "memory")

// ---------------- transposes ----------------
__global__ void k_transpose_in(const float* __restrict__ in, float* __restrict__ out) {
    __shared__ float tile[32][33];
    int b = blockIdx.z, s0 = blockIdx.x * 32, f0 = blockIdx.y * 32;
    int tx = threadIdx.x, ty = threadIdx.y;
    #pragma unroll
    for (int r = ty; r < 32; r += 8)
        tile[r][tx] = in[((size_t)(b * FDIM + f0 + r)) * SEQ + s0 + tx];
    __syncthreads();
    #pragma unroll
    for (int r = ty; r < 32; r += 8)
        out[((size_t)(b * SEQ + s0 + r)) * FDIM + f0 + tx] = tile[tx][r];
}

__global__ void k_transpose_out(const float* __restrict__ y2, float* __restrict__ out) {
    __shared__ float tile[32][33];
    int b = blockIdx.z, s0 = blockIdx.x * 32, f0 = blockIdx.y * 32;
    int tx = threadIdx.x, ty = threadIdx.y;
    #pragma unroll
    for (int r = ty; r < 32; r += 8)
        tile[r][tx] = y2[((size_t)(b * SEQ + s0 + r)) * FDIM + f0 + tx];
    __syncthreads();
    #pragma unroll
    for (int r = ty; r < 32; r += 8)
        out[((size_t)(b * FDIM + f0 + r)) * SEQ + s0 + tx] = tile[tx][r];
}

// w1 [O=3072][I=1024][k=3] -> w1t [k*1024+i][o]
__global__ void k_w1t(const float* __restrict__ w1, float* __restrict__ w1t) {
    __shared__ float tile[32][33];
    int k = blockIdx.z, o0 = blockIdx.x * 32, i0 = blockIdx.y * 32;
    int tx = threadIdx.x, ty = threadIdx.y;
    #pragma unroll
    for (int r = ty; r < 32; r += 8)
        tile[r][tx] = w1[((size_t)(o0 + r) * IDIM + i0 + tx) * 3 + k];
    __syncthreads();
    #pragma unroll
    for (int r = ty; r < 32; r += 8)
        w1t[((size_t)k * IDIM + i0 + r) * TI3 + o0 + tx] = tile[tx][r];
}

// ---------------- gate logits + softmax ----------------
__global__ __launch_bounds__(256) void k_logits(const float* __restrict__ X,
                                                const float* __restrict__ G,
                                                float* __restrict__ gates, int K) {
    __shared__ float Xs[16][65];
    __shared__ float Gs[64][16];
    int t0 = blockIdx.x * 16, tid = threadIdx.x;
    int e = tid & 15, tl = tid >> 4;
    float acc = 0.f;
    for (int k0 = 0; k0 < K; k0 += 64) {
        __syncthreads();
        #pragma unroll
        for (int r = 0; r < 4; r++) {
            int j = tid + 256 * r;
            Xs[j >> 6][j & 63] = X[(size_t)(t0 + (j >> 6)) * K + k0 + (j & 63)];
        }
        #pragma unroll
        for (int r = 0; r < 4; r++) {
            int j = tid + 256 * r;
            Gs[j >> 4][j & 15] = G[(size_t)(k0 + (j >> 4)) * NEXP + (j & 15)];
        }
        __syncthreads();
        #pragma unroll
        for (int k = 0; k < 64; k++) acc += Xs[tl][k] * Gs[k][e];
    }
    float m = acc;
    #pragma unroll
    for (int o = 8; o >= 1; o >>= 1) m = fmaxf(m, __shfl_xor_sync(0xffffffffu, m, o, 16));
    float ex = expf(acc - m);
    float s = ex;
    #pragma unroll
    for (int o = 8; o >= 1; o >>= 1) s += __shfl_xor_sync(0xffffffffu, s, o, 16);
    gates[(size_t)(t0 + tl) * NEXP + e] = ex / s;
}

// ---------------- per-expert descending sort ----------------
extern __shared__ unsigned long long smsort[];
__global__ __launch_bounds__(1024) void k_sort(const float* __restrict__ gates,
                                               int* __restrict__ ord) {
    int e = blockIdx.x, tid = threadIdx.x;
    #pragma unroll
    for (int r = 0; r < 8; r++) {
        int i = r * 1024 + tid;
        unsigned fb = __float_as_uint(gates[(size_t)i * NEXP + e]);
        smsort[i] = ((unsigned long long)fb << 32) | (unsigned)(NTOK - 1 - i);
    }
    __syncthreads();
    for (int k = 2; k <= NTOK; k <<= 1) {
        for (int j = k >> 1; j > 0; j >>= 1) {
            #pragma unroll
            for (int r = 0; r < 8; r++) {
                int i = r * 1024 + tid;
                int l = i ^ j;
                if (l > i) {
                    unsigned long long a = smsort[i], b = smsort[l];
                    bool desc = ((i & k) == 0);
                    if ((a < b) == desc) { smsort[i] = b; smsort[l] = a; }
                }
            }
            __syncthreads();
        }
    }
    #pragma unroll
    for (int r = 0; r < 8; r++) {
        int i = r * 1024 + tid;
        ord[e * NTOK + i] = NTOK - 1 - (int)(unsigned)(smsort[i] & 0xffffffffu);
    }
}

// ---------------- greedy capacity assignment ----------------
__global__ __launch_bounds__(1024) void k_greedy(const int* __restrict__ ord,
                                                 int* __restrict__ perm) {
    __shared__ unsigned assigned[NTOK / 32];
    __shared__ int wsums[32];
    int tid = threadIdx.x, lane = tid & 31, wid = tid >> 5;
    if (tid < NTOK / 32) assigned[tid] = 0u;
    __syncthreads();
    for (int e = 0; e < NEXP; e++) {
        int toks[8];
        int flags = 0, cnt = 0;
        #pragma unroll
        for (int i = 0; i < 8; i++) {
            int tok = ord[e * NTOK + tid * 8 + i];
            toks[i] = tok;
            bool freetok = !((assigned[tok >> 5] >> (tok & 31)) & 1u);
            flags |= ((int)freetok) << i;
            cnt += (int)freetok;
        }
        int v = cnt;
        #pragma unroll
        for (int o = 1; o < 32; o <<= 1) {
            int n = __shfl_up_sync(0xffffffffu, v, o);
            if (lane >= o) v += n;
        }
        if (lane == 31) wsums[wid] = v;
        __syncthreads();
        if (wid == 0) {
            int w = wsums[lane];
            #pragma unroll
            for (int o = 1; o < 32; o <<= 1) {
                int n = __shfl_up_sync(0xffffffffu, w, o);
                if (lane >= o) w += n;
            }
            wsums[lane] = w;
        }
        __syncthreads();
        int r = v - cnt + (wid ? wsums[wid - 1] : 0);
        #pragma unroll
        for (int i = 0; i < 8; i++) {
            if ((flags >> i) & 1) {
                if (r < CAP) {
                    int tok = toks[i];
                    perm[r * NEXP + e] = tok;
                    atomicOr(&assigned[tok >> 5], 1u << (tok & 31));
                }
                r++;
            }
        }
        __syncthreads();
    }
}

__global__ void k_scatter_inv(const int* __restrict__ perm, int* __restrict__ inv) {
    int p = blockIdx.x * 256 + threadIdx.x;
    inv[perm[p]] = p;
}

__global__ void k_scale(const int* __restrict__ inv, const float* __restrict__ gates,
                        float* __restrict__ scl) {
    int t = blockIdx.x * 256 + threadIdx.x;
    scl[t] = gates[(size_t)t * NEXP + (inv[t] >> 9)];
}

// gather token rows (expert-grouped order), scale by gate (same multiply as R1 in-GEMM)
__global__ void k_fgather(const float* __restrict__ X, const int* __restrict__ perm,
                          const float* __restrict__ scl, float* __restrict__ Ag, int K) {
    int col = blockIdx.x * 256 + threadIdx.x;
    int q = blockIdx.y;
    int tok = perm[(q & 511) * NEXP + (q >> 9)];
    Ag[(size_t)q * K + col] = X[(size_t)tok * K + col] * scl[tok];
}

// ================= fp32 pipelined SIMT GEMM (R1-bitwise per-element math) =================
#define KC 16
__global__ __launch_bounds__(256, 2) void k_gemm_f32(
    const float* __restrict__ A, const float* __restrict__ B,
    const int* __restrict__ perm, float* __restrict__ Y,
    int N, int K, int aStride, int isConv)
{
    __shared__ float As[2][KC][128];
    __shared__ float Bs[2][KC][128];
    __shared__ int stok[128];

    int tid = threadIdx.x;
    int e = blockIdx.z, n0 = blockIdx.x * 128, by = blockIdx.y;
    int m0 = isConv ? by * 128 : e * CAP + by * 128;
    if (tid < 128) stok[tid] = perm ? perm[(by * 128 + tid) * NEXP + e] : (m0 + tid);

    const float* Bb = B + (size_t)e * K * N;
    int tx = tid & 15, ty = tid >> 4;
    int rowA = tid >> 2, seg = (tid & 3) * 4;
    int bK = tid >> 4, bC = (tid & 15) * 8;
    uint32_t bs = s2u(&Bs[0][0][0]);

    float acc[8][8];
    #pragma unroll
    for (int i = 0; i < 8; i++)
        #pragma unroll
        for (int j = 0; j < 8; j++) acc[i][j] = 0.f;

    float4 ra0, ra1;
    int L = K / KC;

    #define LOADA(c) do {                                                              \
        int kc = (c) * KC;                                                             \
        if (!isConv) {                                                                 \
            ra0 = *(const float4*)(A + (size_t)(m0 + rowA) * aStride + kc + seg);      \
            ra1 = *(const float4*)(A + (size_t)(m0 + 64 + rowA) * aStride + kc + seg); \
        } else {                                                                       \
            int tap = kc >> 10, ca = (kc & 1023) + seg;                                \
            int rg0 = m0 + rowA, rg1 = m0 + 64 + rowA;                                 \
            ra0 = make_float4(0.f, 0.f, 0.f, 0.f);                                     \
            ra1 = make_float4(0.f, 0.f, 0.f, 0.f);                                     \
            if (((rg0 & (SEQ - 1)) + tap) >= 2)                                        \
                ra0 = *(const float4*)(A + (size_t)(rg0 + tap - 2) * aStride + ca);    \
            if (((rg1 & (SEQ - 1)) + tap) >= 2)                                        \
                ra1 = *(const float4*)(A + (size_t)(rg1 + tap - 2) * aStride + ca);    \
        } } while (0)

    #define CPB(c, s) do {                                                             \
        const float* src = Bb + (size_t)((c) * KC + bK) * N + n0 + bC;                 \
        uint32_t dst = bs + ((((s) * KC + bK) * 128 + bC) << 2);                       \
        cpasync16(dst, src);                                                           \
        cpasync16(dst + 16, src + 4);                                                  \
        CP_COMMIT(); } while (0)

    #define STSA(s) do {                                                               \
        As[s][seg + 0][rowA] = ra0.x; As[s][seg + 1][rowA] = ra0.y;                    \
        As[s][seg + 2][rowA] = ra0.z; As[s][seg + 3][rowA] = ra0.w;                    \
        As[s][seg + 0][64 + rowA] = ra1.x; As[s][seg + 1][64 + rowA] = ra1.y;          \
        As[s][seg + 2][64 + rowA] = ra1.z; As[s][seg + 3][64 + rowA] = ra1.w;          \
    } while (0)

    LOADA(0); CPB(0, 0);
    STSA(0); CP_WAIT0(); __syncthreads();

    for (int c = 0; c < L; c++) {
        int s = c & 1;
        if (c + 1 < L) { LOADA(c + 1); CPB(c + 1, s ^ 1); }
        #pragma unroll
        for (int k = 0; k < KC; k++) {
            float a[8], b[8];
            *(float4*)&a[0] = *(const float4*)&As[s][k][ty * 4];
            *(float4*)&a[4] = *(const float4*)&As[s][k][64 + ty * 4];
            *(float4*)&b[0] = *(const float4*)&Bs[s][k][tx * 4];
            *(float4*)&b[4] = *(const float4*)&Bs[s][k][64 + tx * 4];
            #pragma unroll
            for (int i = 0; i < 8; i++)
                #pragma unroll
                for (int j = 0; j < 8; j++) acc[i][j] += a[i] * b[j];
        }
        if (c + 1 < L) { STSA(s ^ 1); CP_WAIT0(); __syncthreads(); }
    }

    #pragma unroll
    for (int i = 0; i < 8; i++) {
        int r = (i < 4) ? (ty * 4 + i) : (64 + ty * 4 + i - 4);
        int tok = stok[r];
        float* yr = Y + (size_t)tok * N + n0;
        *(float4*)(yr + tx * 4)      = make_float4(acc[i][0], acc[i][1], acc[i][2], acc[i][3]);
        *(float4*)(yr + 64 + tx * 4) = make_float4(acc[i][4], acc[i][5], acc[i][6], acc[i][7]);
    }
}

// ---------------- triple norm ----------------
__global__ __launch_bounds__(256) void k_triple_norm(const float* __restrict__ Y,
                                                     float* __restrict__ Z) {
    __shared__ float sm[8];
    int t = blockIdx.x, tid = threadIdx.x;
    const float* row = Y + (size_t)t * TI3;
    float v[4];
    float ls = 0.f;
    #pragma unroll
    for (int i = 0; i < 4; i++) {
        int c = tid + 256 * i;
        float r = fmaxf(row[c], 0.f);
        v[i] = r * r * r * row[IDIM + c] + row[2 * IDIM + c];
        ls += v[i];
    }
    #pragma unroll
    for (int o = 16; o >= 1; o >>= 1) ls += __shfl_xor_sync(0xffffffffu, ls, o);
    if ((tid & 31) == 0) sm[tid >> 5] = ls;
    __syncthreads();
    float mean = (sm[0] + sm[1] + sm[2] + sm[3] + sm[4] + sm[5] + sm[6] + sm[7]) * (1.0f / 1024.0f);
    __syncthreads();
    float ss = 0.f;
    #pragma unroll
    for (int i = 0; i < 4; i++) { float d = v[i] - mean; ss += d * d; }
    #pragma unroll
    for (int o = 16; o >= 1; o >>= 1) ss += __shfl_xor_sync(0xffffffffu, ss, o);
    if ((tid & 31) == 0) sm[tid >> 5] = ss;
    __syncthreads();
    float tot = sm[0] + sm[1] + sm[2] + sm[3] + sm[4] + sm[5] + sm[6] + sm[7];
    float rstd = sqrtf(1024.0f / tot);
    #pragma unroll
    for (int i = 0; i < 4; i++)
        Z[(size_t)t * IDIM + tid + 256 * i] = (v[i] - mean) * rstd;
}

// ---------------- host ----------------
extern "C" void kernel_launch(void* const* d_in, const int* in_sizes, int n_in,
                              void* d_out, int out_size) {
    const float* inp   = (const float*)d_in[0];
    const float* w0    = (const float*)d_in[1];
    const float* gate0 = (const float*)d_in[2];
    const float* w1    = (const float*)d_in[3];
    const float* w2    = (const float*)d_in[4];
    const float* gate2 = (const float*)d_in[5];
    float* out = (float*)d_out;

    void* p;  cudaGetSymbolAddress(&p, g_scratch);
    void* pi; cudaGetSymbolAddress(&pi, g_iscr);
    float* fs = (float*)p;
    int*   is = (int*)pi;

    float* xin   = fs + OFF_XIN;
    float* big   = fs + OFF_BIG;
    float* tn1   = fs + OFF_TN1;
    float* tn2   = fs + OFF_TN2;
    float* y2    = fs + OFF_Y2;
    float* gates = fs + OFF_GATES;
    float* scl   = fs + OFF_SCALE;
    float* w1t   = fs + OFF_W1T;
    float* Ag    = fs + OFF_AG;
    int* ord  = is;
    int* perm = is + 131072;
    int* inv  = is + 131072 + 8192;

    cudaFuncSetAttribute(k_sort, cudaFuncAttributeMaxDynamicSharedMemorySize, 65536);

    // ---- MoE 1 ----
    k_transpose_in<<<dim3(64, 16, 4), dim3(32, 8)>>>(inp, xin);
    k_logits<<<512, 256>>>(xin, gate0, gates, FDIM);
    k_sort<<<16, 1024, 65536>>>(gates, ord);
    k_greedy<<<1, 1024>>>(ord, perm);
    k_scatter_inv<<<32, 256>>>(perm, inv);
    k_scale<<<32, 256>>>(inv, gates, scl);
    k_fgather<<<dim3(2, 8192), 256>>>(xin, perm, scl, Ag, FDIM);
    k_gemm_f32<<<dim3(24, 4, 16), 256>>>(Ag, w0, perm, big, TI3, FDIM, FDIM, 0);
    k_triple_norm<<<8192, 256>>>(big, tn1);

    // ---- causal conv (one GEMM, logical K = 3*1024, shifted A) ----
    k_w1t<<<dim3(96, 32, 3), dim3(32, 8)>>>(w1, w1t);
    k_gemm_f32<<<dim3(24, 64, 1), 256>>>(tn1, w1t, nullptr, big, TI3, TI3, IDIM, 1);
    k_triple_norm<<<8192, 256>>>(big, tn2);

    // ---- MoE 2 ----
    k_logits<<<512, 256>>>(tn2, gate2, gates, IDIM);
    k_sort<<<16, 1024, 65536>>>(gates, ord);
    k_greedy<<<1, 1024>>>(ord, perm);
    k_scatter_inv<<<32, 256>>>(perm, inv);
    k_scale<<<32, 256>>>(inv, gates, scl);
    k_fgather<<<dim3(4, 8192), 256>>>(tn2, perm, scl, Ag, IDIM);
    k_gemm_f32<<<dim3(4, 4, 16), 256>>>(Ag, w2, perm, y2, FDIM, IDIM, IDIM, 0);

    k_transpose_out<<<dim3(64, 16, 4), dim3(32, 8)>>>(y2, out);
}